// round 15
// baseline (speedup 1.0000x reference)
#include <cuda_runtime.h>
#include <cuda_bf16.h>
#include <math.h>

#define NTHREADS 256
#define HIDDEN 256

// Fused sphere-trace + color-MLP renderer.
//
// The hit mask (sdf < 1e-8) is decided by ulp-level stall dynamics -> must
// replicate the reference bit-exactly. Final model (fits all 14 rounds to
// 3 decimals, additively):
//   LOOP (jitted fori_loop fusion, fully contracted):
//     p    = fma(t, d, o)
//     q    = p - c
//     s    = fma(qz,qz, fma(qx,qx, rn(qy*qy)))     [S5 chain]
//     dist = sqrt.rn(s) - r;  t += dist   (63 updates)
//   POINTS (eager elementwise kernels, NO contraction):
//     p    = rn(o + rn(t*d))                        [plain, incl. pz]
//   MASK (eager norm = reduce fusion; square contracts into the accumulate
//         chain -> SAME S5 chain, but consuming the plain points):
//     q    = p - c
//     s    = fma(qz,qz, fma(qx,qx, rn(qy*qy)))     [S5 chain]
//     dist = sqrt.rn(s) - r;  hit = dist < 1e-8
__global__ __launch_bounds__(NTHREADS)
void sphere_mlp_kernel(const float* __restrict__ origins,
                       const float* __restrict__ directions,
                       const float* __restrict__ center,
                       const float* __restrict__ radius,
                       const float* __restrict__ W1,
                       const float* __restrict__ b1,
                       const float* __restrict__ W2,
                       const float* __restrict__ b2,
                       const int*   __restrict__ max_iters,
                       float* __restrict__ out,
                       int N)
{
    __shared__ float4 sw1[HIDDEN];
    __shared__ float4 sw2[HIDDEN];
    __shared__ float  sb2[3];

    const int tid = threadIdx.x;
    for (int j = tid; j < HIDDEN; j += NTHREADS) {
        sw1[j] = make_float4(W1[j], W1[HIDDEN + j], W1[2 * HIDDEN + j], b1[j]);
        sw2[j] = make_float4(W2[3 * j + 0], W2[3 * j + 1], W2[3 * j + 2], 0.0f);
    }
    if (tid < 3) sb2[tid] = b2[tid];
    __syncthreads();

    const int i = blockIdx.x * NTHREADS + tid;
    if (i >= N) return;

    const float cx = center[0], cy = center[1], cz = center[2];
    const float r  = radius[0];
    const int iters = max_iters[0] - 1;   // reference does max_iters-1 updates

    const float ox = origins[3 * i + 0];
    const float oy = origins[3 * i + 1];
    const float oz = origins[3 * i + 2];
    const float dx = directions[3 * i + 0];
    const float dy = directions[3 * i + 1];
    const float dz = directions[3 * i + 2];

    // --- LOOP recipe: fma-p, S5 fused reduce ---
    float t = 0.0f;
    bool certified_miss = false;
    for (int it = 0; it < iters; ++it) {
        const float px = fmaf(t, dx, ox);
        const float py = fmaf(t, dy, oy);
        const float pz = fmaf(t, dz, oz);
        const float qx = __fsub_rn(px, cx);
        const float qy = __fsub_rn(py, cy);
        const float qz = __fsub_rn(pz, cz);
        const float s  = fmaf(qz, qz, fmaf(qx, qx, __fmul_rn(qy, qy)));
        const float dist = __fsub_rn(__fsqrt_rn(s), r);
        const float tn = __fadd_rn(t, dist);
        if (tn == t) { t = tn; break; }   // exact fixed point: all future updates are no-ops
        t = tn;
        if (dist > 8.0f) { certified_miss = true; break; }  // dist >= t-4, monotone: provably miss
    }

    float* o = out + 3 * i;

    if (certified_miss) {
        o[0] = 0.0f; o[1] = 0.0f; o[2] = 0.0f;
        return;
    }

    // --- POINTS: eager, plain rn (incl. pz) ---
    const float px = __fadd_rn(ox, __fmul_rn(t, dx));
    const float py = __fadd_rn(oy, __fmul_rn(t, dy));
    const float pz = __fadd_rn(oz, __fmul_rn(t, dz));

    // --- MASK: S5 fused chain on the PLAIN points ---
    const float qx = __fsub_rn(px, cx);
    const float qy = __fsub_rn(py, cy);
    const float qz = __fsub_rn(pz, cz);
    const float s  = fmaf(qz, qz, fmaf(qx, qx, __fmul_rn(qy, qy)));
    const float dist = __fsub_rn(__fsqrt_rn(s), r);
    const bool hit = (dist < 1e-8f);

    if (!hit) {
        o[0] = 0.0f; o[1] = 0.0f; o[2] = 0.0f;
        return;
    }

    // --- color MLP on the plain points (only ~1e-3 relative accuracy needed) ---
    float a0 = sb2[0], a1 = sb2[1], a2 = sb2[2];
#pragma unroll 8
    for (int j = 0; j < HIDDEN; ++j) {
        const float4 w = sw1[j];
        const float h = fmaxf(fmaf(px, w.x, fmaf(py, w.y, fmaf(pz, w.z, w.w))), 0.0f);
        const float4 v = sw2[j];
        a0 = fmaf(h, v.x, a0);
        a1 = fmaf(h, v.y, a1);
        a2 = fmaf(h, v.z, a2);
    }

    o[0] = 1.0f / (1.0f + expf(-a0));
    o[1] = 1.0f / (1.0f + expf(-a1));
    o[2] = 1.0f / (1.0f + expf(-a2));
}

extern "C" void kernel_launch(void* const* d_in, const int* in_sizes, int n_in,
                              void* d_out, int out_size) {
    const float* origins    = (const float*)d_in[0];
    const float* directions = (const float*)d_in[1];
    const float* center     = (const float*)d_in[2];
    const float* radius     = (const float*)d_in[3];
    const float* W1         = (const float*)d_in[4];
    const float* b1         = (const float*)d_in[5];
    const float* W2         = (const float*)d_in[6];
    const float* b2         = (const float*)d_in[7];
    const int*   max_iters  = (const int*)d_in[8];
    float* out = (float*)d_out;

    const int N = in_sizes[0] / 3;
    const int blocks = (N + NTHREADS - 1) / NTHREADS;
    sphere_mlp_kernel<<<blocks, NTHREADS>>>(origins, directions, center, radius,
                                            W1, b1, W2, b2, max_iters, out, N);
}

// round 16
// speedup vs baseline: 1.0102x; 1.0102x over previous
#include <cuda_runtime.h>
#include <cuda_bf16.h>
#include <math.h>
#include <stdint.h>

#define NTHREADS 256
#define HIDDEN 256

// Fused sphere-trace + color-MLP renderer.
//
// TRACE/MASK RECIPE IS BIT-EXACT AGAINST THE REFERENCE — DO NOT TOUCH:
//   LOOP (jitted fori_loop fusion, fully contracted):
//     p = fma(t,d,o); q = p - c; s = fma(qz,qz, fma(qx,qx, rn(qy*qy)));
//     dist = sqrt.rn(s) - r; t += dist   (63 updates)
//   POINTS (eager, plain rn):  p = rn(o + rn(t*d))
//   MASK (eager norm reduce, S5 chain on plain points): hit = dist < 1e-8
//
// MLP optimization: hidden units processed in pairs with packed fma.rn.f32x2
// (FFMA2). Shared weights repacked so pairs are contiguous float4s; ray coords
// duplicated into both lanes once; accumulators kept packed, lane-reduced at
// the end. 8 math ops + 4 LDS.128 per 2 units (vs 14 + 4 scalar).

__device__ __forceinline__ uint64_t pack2(float lo, float hi) {
    uint64_t v;
    asm("mov.b64 %0, {%1, %2};" : "=l"(v) : "f"(lo), "f"(hi));
    return v;
}
__device__ __forceinline__ void unpack2(uint64_t v, float& lo, float& hi) {
    asm("mov.b64 {%0, %1}, %2;" : "=f"(lo), "=f"(hi) : "l"(v));
}
__device__ __forceinline__ uint64_t fma2(uint64_t a, uint64_t b, uint64_t c) {
    uint64_t d;
    asm("fma.rn.f32x2 %0, %1, %2, %3;" : "=l"(d) : "l"(a), "l"(b), "l"(c));
    return d;
}

__global__ __launch_bounds__(NTHREADS)
void sphere_mlp_kernel(const float* __restrict__ origins,
                       const float* __restrict__ directions,
                       const float* __restrict__ center,
                       const float* __restrict__ radius,
                       const float* __restrict__ W1,
                       const float* __restrict__ b1,
                       const float* __restrict__ W2,
                       const float* __restrict__ b2,
                       const int*   __restrict__ max_iters,
                       float* __restrict__ out,
                       int N)
{
    // Packed pair layout (pair p = units j0=2p, j1=2p+1):
    //   l1a[p] = (W1x[j0], W1x[j1], W1y[j0], W1y[j1])
    //   l1b[p] = (W1z[j0], W1z[j1], b1[j0],  b1[j1])
    //   l2a[p] = (W2x[j0], W2x[j1], W2y[j0], W2y[j1])
    //   l2b[p] = (W2z[j0], W2z[j1], 0, 0)
    __shared__ float4 l1a[HIDDEN / 2];
    __shared__ float4 l1b[HIDDEN / 2];
    __shared__ float4 l2a[HIDDEN / 2];
    __shared__ float4 l2b[HIDDEN / 2];
    __shared__ float  sb2[3];

    const int tid = threadIdx.x;
    for (int p = tid; p < HIDDEN / 2; p += NTHREADS) {
        const int j0 = 2 * p, j1 = 2 * p + 1;
        l1a[p] = make_float4(W1[j0],           W1[j1],
                             W1[HIDDEN + j0],  W1[HIDDEN + j1]);
        l1b[p] = make_float4(W1[2 * HIDDEN + j0], W1[2 * HIDDEN + j1],
                             b1[j0],              b1[j1]);
        l2a[p] = make_float4(W2[3 * j0 + 0], W2[3 * j1 + 0],
                             W2[3 * j0 + 1], W2[3 * j1 + 1]);
        l2b[p] = make_float4(W2[3 * j0 + 2], W2[3 * j1 + 2], 0.0f, 0.0f);
    }
    if (tid < 3) sb2[tid] = b2[tid];
    __syncthreads();

    const int i = blockIdx.x * NTHREADS + tid;
    if (i >= N) return;

    const float cx = center[0], cy = center[1], cz = center[2];
    const float r  = radius[0];
    const int iters = max_iters[0] - 1;   // reference does max_iters-1 updates

    const float ox = origins[3 * i + 0];
    const float oy = origins[3 * i + 1];
    const float oz = origins[3 * i + 2];
    const float dx = directions[3 * i + 0];
    const float dy = directions[3 * i + 1];
    const float dz = directions[3 * i + 2];

    // --- LOOP recipe: fma-p, S5 fused reduce (BIT-EXACT, frozen) ---
    float t = 0.0f;
    bool certified_miss = false;
    for (int it = 0; it < iters; ++it) {
        const float px = fmaf(t, dx, ox);
        const float py = fmaf(t, dy, oy);
        const float pz = fmaf(t, dz, oz);
        const float qx = __fsub_rn(px, cx);
        const float qy = __fsub_rn(py, cy);
        const float qz = __fsub_rn(pz, cz);
        const float s  = fmaf(qz, qz, fmaf(qx, qx, __fmul_rn(qy, qy)));
        const float dist = __fsub_rn(__fsqrt_rn(s), r);
        const float tn = __fadd_rn(t, dist);
        if (tn == t) { t = tn; break; }   // exact fixed point: all future updates are no-ops
        t = tn;
        if (dist > 8.0f) { certified_miss = true; break; }  // dist >= t-4, monotone: provably miss
    }

    float* o = out + 3 * i;

    if (certified_miss) {
        o[0] = 0.0f; o[1] = 0.0f; o[2] = 0.0f;
        return;
    }

    // --- POINTS: eager, plain rn (BIT-EXACT, frozen) ---
    const float px = __fadd_rn(ox, __fmul_rn(t, dx));
    const float py = __fadd_rn(oy, __fmul_rn(t, dy));
    const float pz = __fadd_rn(oz, __fmul_rn(t, dz));

    // --- MASK: S5 fused chain on the PLAIN points (BIT-EXACT, frozen) ---
    const float qx = __fsub_rn(px, cx);
    const float qy = __fsub_rn(py, cy);
    const float qz = __fsub_rn(pz, cz);
    const float s  = fmaf(qz, qz, fmaf(qx, qx, __fmul_rn(qy, qy)));
    const float dist = __fsub_rn(__fsqrt_rn(s), r);
    const bool hit = (dist < 1e-8f);

    if (!hit) {
        o[0] = 0.0f; o[1] = 0.0f; o[2] = 0.0f;
        return;
    }

    // --- color MLP, packed f32x2 over hidden-unit pairs (~1e-3 budget) ---
    const uint64_t px2 = pack2(px, px);
    const uint64_t py2 = pack2(py, py);
    const uint64_t pz2 = pack2(pz, pz);

    uint64_t A0 = 0, A1 = 0, A2 = 0;   // packed (even, odd) accumulators, (+0,+0)

#pragma unroll 8
    for (int p = 0; p < HIDDEN / 2; ++p) {
        const float4 wa = l1a[p];                  // (wx0, wx1, wy0, wy1)
        const float4 wb = l1b[p];                  // (wz0, wz1, b0,  b1)
        uint64_t h2 = fma2(px2, pack2(wa.x, wa.y),
                     fma2(py2, pack2(wa.z, wa.w),
                     fma2(pz2, pack2(wb.x, wb.y), pack2(wb.z, wb.w))));
        float h0, h1;
        unpack2(h2, h0, h1);
        h0 = fmaxf(h0, 0.0f);
        h1 = fmaxf(h1, 0.0f);
        h2 = pack2(h0, h1);

        const float4 va = l2a[p];                  // (vx0, vx1, vy0, vy1)
        const float4 vb = l2b[p];                  // (vz0, vz1, 0, 0)
        A0 = fma2(h2, pack2(va.x, va.y), A0);
        A1 = fma2(h2, pack2(va.z, va.w), A1);
        A2 = fma2(h2, pack2(vb.x, vb.y), A2);
    }

    float a0l, a0h, a1l, a1h, a2l, a2h;
    unpack2(A0, a0l, a0h);
    unpack2(A1, a1l, a1h);
    unpack2(A2, a2l, a2h);
    const float a0 = sb2[0] + a0l + a0h;
    const float a1 = sb2[1] + a1l + a1h;
    const float a2 = sb2[2] + a2l + a2h;

    o[0] = 1.0f / (1.0f + expf(-a0));
    o[1] = 1.0f / (1.0f + expf(-a1));
    o[2] = 1.0f / (1.0f + expf(-a2));
}

extern "C" void kernel_launch(void* const* d_in, const int* in_sizes, int n_in,
                              void* d_out, int out_size) {
    const float* origins    = (const float*)d_in[0];
    const float* directions = (const float*)d_in[1];
    const float* center     = (const float*)d_in[2];
    const float* radius     = (const float*)d_in[3];
    const float* W1         = (const float*)d_in[4];
    const float* b1         = (const float*)d_in[5];
    const float* W2         = (const float*)d_in[6];
    const float* b2         = (const float*)d_in[7];
    const int*   max_iters  = (const int*)d_in[8];
    float* out = (float*)d_out;

    const int N = in_sizes[0] / 3;
    const int blocks = (N + NTHREADS - 1) / NTHREADS;
    sphere_mlp_kernel<<<blocks, NTHREADS>>>(origins, directions, center, radius,
                                            W1, b1, W2, b2, max_iters, out, N);
}